// round 11
// baseline (speedup 1.0000x reference)
#include <cuda_runtime.h>
#include <cuda_fp16.h>
#include <math.h>
#include <cstdint>

#define D 128
#define NMAX 150000
#define NNZMAX 4800000
#define LBUF 4
#define NEG_SLOPE 0.2f
#define REG_LAMBDA 1e-4f
#define PADK 136   // smem row stride (fp16 elems) for conflict-free ldmatrix
#define PADS 132   // stage row stride (fp32 elems)

// ---------------- static device scratch ----------------
__device__ uint8_t g_ego_f8[(size_t)NMAX * D];          // working embeddings (e4m3)
__device__ __half  g_side_h[(size_t)NMAX * D];          // A @ ego (fp16)
__device__ __half  g_norm_h[(size_t)LBUF * NMAX * D];   // normalized per-layer outputs (fp16)
__device__ int     g_rowptr[NMAX + 1];
__device__ int     g_counts[NMAX];                      // zero at module load; re-zeroed by k_finalize
__device__ int     g_cursor[NMAX];
__device__ int2    g_cv[NNZMAX];
__device__ int     g_scanex[NMAX + 1024];
__device__ int     g_blocksums[1024];
__device__ int     g_blockoff[1024];
// weights fp16, n-major: [layer][chunk(Wg/Wb)][n][k]
__device__ __half  g_Bw[(size_t)LBUF * 2 * 16384];

// ---------------- helpers ----------------
__device__ __forceinline__ uint32_t smem_u32(const void* p) {
    uint32_t a;
    asm("{ .reg .u64 t; cvta.to.shared.u64 t, %1; cvt.u32.u64 %0, t; }" : "=r"(a) : "l"(p));
    return a;
}
__device__ __forceinline__ void ldmx4(uint32_t& r0, uint32_t& r1, uint32_t& r2, uint32_t& r3,
                                      uint32_t addr) {
    asm volatile("ldmatrix.sync.aligned.m8n8.x4.shared.b16 {%0,%1,%2,%3}, [%4];"
                 : "=r"(r0), "=r"(r1), "=r"(r2), "=r"(r3) : "r"(addr));
}
__device__ __forceinline__ void mma_f16(float* c, const uint32_t* a, const uint32_t* b) {
    asm volatile(
        "mma.sync.aligned.m16n8k16.row.col.f32.f16.f16.f32 "
        "{%0,%1,%2,%3}, {%4,%5,%6,%7}, {%8,%9}, {%0,%1,%2,%3};"
        : "+f"(c[0]), "+f"(c[1]), "+f"(c[2]), "+f"(c[3])
        : "r"(a[0]), "r"(a[1]), "r"(a[2]), "r"(a[3]), "r"(b[0]), "r"(b[1]));
}
// expand 4 packed e4m3 (u32) -> two f16x2 (column order preserved)
__device__ __forceinline__ void f8x4_to_h2x2(uint32_t in, uint32_t& f0, uint32_t& f1) {
    asm("{ .reg .b16 lo, hi;\n\t"
        "mov.b32 {lo, hi}, %2;\n\t"
        "cvt.rn.f16x2.e4m3x2 %0, lo;\n\t"
        "cvt.rn.f16x2.e4m3x2 %1, hi; }"
        : "=r"(f0), "=r"(f1) : "r"(in));
}
// pack 4 floats -> 4 e4m3 bytes (v0 lowest byte)
__device__ __forceinline__ uint32_t f32x4_to_f8x4(float v0, float v1, float v2, float v3) {
    uint16_t lo, hi;
    asm("cvt.rn.satfinite.e4m3x2.f32 %0, %1, %2;" : "=h"(lo) : "f"(v1), "f"(v0));
    asm("cvt.rn.satfinite.e4m3x2.f32 %0, %1, %2;" : "=h"(hi) : "f"(v3), "f"(v2));
    return (uint32_t)lo | ((uint32_t)hi << 16);
}

// ---------------- init: e4m3 ego, edge count (counts pre-zeroed), zero out ----------------
__global__ void k_init(const float* __restrict__ ue, const float* __restrict__ ie,
                       const int* __restrict__ er, int nnz, int U, int I, float* out) {
    size_t uN = (size_t)U * D;
    size_t n  = (size_t)(U + I) * D;
    for (size_t i4 = (size_t)blockIdx.x * blockDim.x + threadIdx.x; i4 * 4 < n;
         i4 += (size_t)gridDim.x * blockDim.x) {
        size_t i = i4 * 4;  // uN is a multiple of 128, chunks never straddle
        const float* src = (i < uN) ? (ue + i) : (ie + (i - uN));
        float4 v = *(const float4*)src;
        ((uint32_t*)g_ego_f8)[i4] = f32x4_to_f8x4(v.x, v.y, v.z, v.w);
    }
    for (int e = blockIdx.x * blockDim.x + threadIdx.x; e < nnz; e += gridDim.x * blockDim.x)
        atomicAdd(&g_counts[er[e]], 1);
    if (blockIdx.x == 0 && threadIdx.x < 2) out[threadIdx.x] = 0.f;
}

// ---------------- CSR build ----------------
__global__ void k_scan_blocks(int N) {
    int i = blockIdx.x * 1024 + threadIdx.x;
    int c = (i < N) ? g_counts[i] : 0;
    int lane = threadIdx.x & 31, warp = threadIdx.x >> 5;
    int v = c;
#pragma unroll
    for (int o = 1; o < 32; o <<= 1) {
        int t = __shfl_up_sync(0xffffffffu, v, o);
        if (lane >= o) v += t;
    }
    __shared__ int wsum[32];
    if (lane == 31) wsum[warp] = v;
    __syncthreads();
    if (warp == 0) {
        int w = wsum[lane];
#pragma unroll
        for (int o = 1; o < 32; o <<= 1) {
            int t = __shfl_up_sync(0xffffffffu, w, o);
            if (lane >= o) w += t;
        }
        wsum[lane] = w;
    }
    __syncthreads();
    int woff = (warp > 0) ? wsum[warp - 1] : 0;
    g_scanex[i] = v + woff - c;
    if (threadIdx.x == 0) g_blocksums[blockIdx.x] = wsum[31];
}
__global__ void k_scan_sums(int nb) {
    int t = threadIdx.x;
    int v = (t < nb) ? g_blocksums[t] : 0;
    int lane = t & 31, warp = t >> 5;
    int x = v;
#pragma unroll
    for (int o = 1; o < 32; o <<= 1) {
        int s = __shfl_up_sync(0xffffffffu, x, o);
        if (lane >= o) x += s;
    }
    __shared__ int wsum[8];
    if (lane == 31) wsum[warp] = x;
    __syncthreads();
    if (warp == 0 && lane < 8) {
        int w = wsum[lane];
#pragma unroll
        for (int o = 1; o < 8; o <<= 1) {
            int s = __shfl_up_sync(0xffu, w, o);
            if (lane >= o) w += s;
        }
        wsum[lane] = w;
    }
    __syncthreads();
    int woff = (warp > 0) ? wsum[warp - 1] : 0;
    if (t < nb) g_blockoff[t] = (x + woff) - v;
}
__global__ void k_finalize(int N, int nnz) {
    int gid = blockIdx.x * blockDim.x + threadIdx.x;
    for (int i = gid; i < N; i += gridDim.x * blockDim.x) {
        int r = g_scanex[i] + g_blockoff[i >> 10];
        g_rowptr[i] = r;
        g_cursor[i] = r;
        g_counts[i] = 0;  // re-zero for next replay (k_init counts into these)
    }
    if (gid == 0) g_rowptr[N] = nnz;
}
__global__ void k_fill(const int* __restrict__ er, const int* __restrict__ ec,
                       const float* __restrict__ ev, int nnz) {
    for (int e = blockIdx.x * blockDim.x + threadIdx.x; e < nnz; e += gridDim.x * blockDim.x) {
        int r = er[e];
        int pos = atomicAdd(&g_cursor[r], 1);
        g_cv[pos] = make_int2(ec[e], __float_as_int(ev[e]));
    }
}

// ---------------- weight prep: fp16 n-major B images ----------------
__global__ void k_prep(const float* __restrict__ Wg, const float* __restrict__ Wb, int L) {
    int idx = blockIdx.x * blockDim.x + threadIdx.x;
    int tot = L * 2 * 16384;
    if (idx >= tot) return;
    int l = idx / 32768;
    int rem = idx - l * 32768;
    int c = rem >> 14;
    int e = rem & 16383;
    int k = e >> 7, n = e & 127;
    const float* W = c ? Wb : Wg;
    float w = W[(size_t)l * 16384 + k * 128 + n];
    g_Bw[(size_t)(l * 2 + c) * 16384 + n * 128 + k] = __float2half(w);
}

// ---------------- SpMM: side = A @ ego (fp8 gather), quarter-warp per edge ----------------
// 4 groups of 8 lanes; each lane loads uint4 (16 e4m3) -> 4 edges in flight per warp
__global__ void k_spmm(int N) {
    int gw = (blockIdx.x * blockDim.x + threadIdx.x) >> 5;
    if (gw >= N) return;
    int lane = threadIdx.x & 31;
    int grp = lane >> 3, hl = lane & 7;
    int s = g_rowptr[gw], e = g_rowptr[gw + 1];
    const uint4* ego16 = (const uint4*)g_ego_f8;  // row = 8 uint4 (128B)
    float acc[16];
#pragma unroll
    for (int q = 0; q < 16; q++) acc[q] = 0.f;
#pragma unroll 2
    for (int j = s + grp; j < e; j += 4) {
        int2 cv = __ldg(&g_cv[j]);
        float v = __int_as_float(cv.y);
        uint4 h = __ldg(&ego16[(size_t)cv.x * 8 + hl]);
        uint32_t f[8];
        f8x4_to_h2x2(h.x, f[0], f[1]);
        f8x4_to_h2x2(h.y, f[2], f[3]);
        f8x4_to_h2x2(h.z, f[4], f[5]);
        f8x4_to_h2x2(h.w, f[6], f[7]);
#pragma unroll
        for (int q = 0; q < 8; q++) {
            float2 a = __half22float2(*(__half2*)&f[q]);
            acc[q * 2]     = fmaf(v, a.x, acc[q * 2]);
            acc[q * 2 + 1] = fmaf(v, a.y, acc[q * 2 + 1]);
        }
    }
    // combine the 4 groups (same hl across groups differs by lane bits 3,4)
#pragma unroll
    for (int q = 0; q < 16; q++) {
        acc[q] += __shfl_xor_sync(0xffffffffu, acc[q], 8);
        acc[q] += __shfl_xor_sync(0xffffffffu, acc[q], 16);
    }
    if (grp == 0) {
        __half2 h[8];
#pragma unroll
        for (int q = 0; q < 8; q++) h[q] = __floats2half2_rn(acc[q * 2], acc[q * 2 + 1]);
        uint4* dst = (uint4*)g_side_h + (size_t)gw * 16 + hl * 2;
        dst[0] = make_uint4(*(uint32_t*)&h[0], *(uint32_t*)&h[1],
                            *(uint32_t*)&h[2], *(uint32_t*)&h[3]);
        dst[1] = make_uint4(*(uint32_t*)&h[4], *(uint32_t*)&h[5],
                            *(uint32_t*)&h[6], *(uint32_t*)&h[7]);
    }
}

// ---------------- fused dense layer via mma.sync fp16 ----------------
// smem: [0,512) bias | [512,1024) srn | A(34816) | B(34816)  => 70656 B, 2 CTAs/SM
#define SM_HDR   1024
#define SM_A     SM_HDR
#define SM_B     (SM_HDR + 34816)
#define SM_TOTAL (SM_HDR + 69632)
// stage (fp32, stride PADS): 128*132*4 = 67584 <= 69632, overlaps A+B post-MMA

__global__ void __launch_bounds__(256, 2) k_layer(const float* __restrict__ bg,
                                                  const float* __restrict__ bb,
                                                  int layer, int N) {
    extern __shared__ char sm[];
    uint32_t smb = smem_u32(sm);
    int tid = threadIdx.x;
    int warp = tid >> 5, lane = tid & 31;
    int row0 = blockIdx.x * 128;

    if (tid < 128) ((float*)sm)[tid] = bg[tid] + bb[tid];

    int rw0 = (warp >> 1) * 32;
    int cw0 = (warp & 1) * 64;

    float cacc[2][8][4];
#pragma unroll
    for (int mt = 0; mt < 2; mt++)
#pragma unroll
        for (int nt = 0; nt < 8; nt++)
#pragma unroll
            for (int q = 0; q < 4; q++) cacc[mt][nt][q] = 0.f;

    for (int chunk = 0; chunk < 2; chunk++) {
        if (chunk) __syncthreads();
        // weights (fp16), pad rows to PADK
        {
            const __half* src = g_Bw + (size_t)(layer * 2 + chunk) * 16384;
            for (int i = tid; i < 2048; i += 256) {
                int n = i >> 4, k8 = (i & 15) * 8;
                *(uint4*)(sm + SM_B + (n * PADK + k8) * 2) = *(const uint4*)(src + n * 128 + k8);
            }
        }
        // A tile: chunk0 = side (fp16 copy), chunk1 = ego(fp8->fp16) * side
        if (chunk == 0) {
            const uint4* s16 = (const uint4*)g_side_h;
            for (int i = tid; i < 2048; i += 256) {
                int r = i >> 4, c = i & 15;
                int gr = row0 + r;
                uint4 v = make_uint4(0u, 0u, 0u, 0u);
                if (gr < N) v = __ldg(&s16[(size_t)gr * 16 + c]);
                *(uint4*)(sm + SM_A + (r * PADK + c * 8) * 2) = v;
            }
        } else {
            const uint4* s16 = (const uint4*)g_side_h;
            const uint2* e8  = (const uint2*)g_ego_f8;
            for (int i = tid; i < 2048; i += 256) {
                int r = i >> 4, c = i & 15;
                int gr = row0 + r;
                uint4 v = make_uint4(0u, 0u, 0u, 0u);
                if (gr < N) {
                    uint4 sv = __ldg(&s16[(size_t)gr * 16 + c]);
                    uint2 ev = __ldg(&e8[(size_t)gr * 16 + c]);
                    uint32_t e0, e1, e2, e3;
                    f8x4_to_h2x2(ev.x, e0, e1);
                    f8x4_to_h2x2(ev.y, e2, e3);
                    __half2* sp = (__half2*)&sv;
                    sp[0] = __hmul2(sp[0], *(__half2*)&e0);
                    sp[1] = __hmul2(sp[1], *(__half2*)&e1);
                    sp[2] = __hmul2(sp[2], *(__half2*)&e2);
                    sp[3] = __hmul2(sp[3], *(__half2*)&e3);
                    v = sv;
                }
                *(uint4*)(sm + SM_A + (r * PADK + c * 8) * 2) = v;
            }
        }
        __syncthreads();

        int t = lane >> 3, rr = lane & 7;
        int roff = (t & 1) * 8 + rr;
        int koff = (t >> 1) * 8;
#pragma unroll
        for (int kk = 0; kk < 8; kk++) {
            int k0 = kk * 16 + koff;
            uint32_t ah[2][4];
#pragma unroll
            for (int mt = 0; mt < 2; mt++) {
                uint32_t a = smb + SM_A + ((rw0 + mt * 16 + roff) * PADK + k0) * 2;
                ldmx4(ah[mt][0], ah[mt][1], ah[mt][2], ah[mt][3], a);
            }
            uint32_t bh[8][2];
#pragma unroll
            for (int np = 0; np < 4; np++) {
                uint32_t a = smb + SM_B + ((cw0 + np * 16 + roff) * PADK + k0) * 2;
                uint32_t r0, r1, r2, r3;
                ldmx4(r0, r1, r2, r3, a);
                bh[np * 2][0] = r0; bh[np * 2][1] = r2;
                bh[np * 2 + 1][0] = r1; bh[np * 2 + 1][1] = r3;
            }
#pragma unroll
            for (int mt = 0; mt < 2; mt++)
#pragma unroll
                for (int nt = 0; nt < 8; nt++) mma_f16(cacc[mt][nt], ah[mt], bh[nt]);
        }
    }
    __syncthreads();

    // epilogue: bias + leaky-relu -> stage
    float* stage = (float*)(sm + SM_HDR);
    const float* sbias = (const float*)sm;
    float* srn = (float*)(sm + 512);
    int g = lane >> 2, tig = lane & 3;
#pragma unroll
    for (int mt = 0; mt < 2; mt++)
#pragma unroll
        for (int nt = 0; nt < 8; nt++) {
            int col = cw0 + nt * 8 + tig * 2;
            int r0 = rw0 + mt * 16 + g;
            float b0 = sbias[col], b1 = sbias[col + 1];
            float v0 = cacc[mt][nt][0] + b0;
            float v1 = cacc[mt][nt][1] + b1;
            float v2 = cacc[mt][nt][2] + b0;
            float v3 = cacc[mt][nt][3] + b1;
            v0 = (v0 > 0.f) ? v0 : NEG_SLOPE * v0;
            v1 = (v1 > 0.f) ? v1 : NEG_SLOPE * v1;
            v2 = (v2 > 0.f) ? v2 : NEG_SLOPE * v2;
            v3 = (v3 > 0.f) ? v3 : NEG_SLOPE * v3;
            stage[r0 * PADS + col] = v0;
            stage[r0 * PADS + col + 1] = v1;
            stage[(r0 + 8) * PADS + col] = v2;
            stage[(r0 + 8) * PADS + col + 1] = v3;
        }
    __syncthreads();

    // row norms: warp w -> rows [w*16, w*16+16)
    for (int rr = 0; rr < 16; rr++) {
        int r = warp * 16 + rr;
        float4 x = *(float4*)&stage[r * PADS + lane * 4];
        float ss = x.x * x.x + x.y * x.y + x.z * x.z + x.w * x.w;
#pragma unroll
        for (int o = 16; o > 0; o >>= 1) ss += __shfl_xor_sync(0xffffffffu, ss, o);
        if (lane == 0) srn[r] = 1.f / fmaxf(sqrtf(ss), 1e-12f);
    }
    __syncthreads();

    // writeout: ego (e4m3) + norm (fp16)
    int rows = N - row0;
    if (rows > 128) rows = 128;
    __half* nout = g_norm_h + (size_t)layer * NMAX * D;
    for (int idx = tid; idx < rows * 32; idx += 256) {
        int r = idx >> 5, q = idx & 31;
        float4 v = *(float4*)&stage[r * PADS + q * 4];
        float rn = srn[r];
        size_t gq = (size_t)(row0 + r) * 32 + q;
        ((uint32_t*)g_ego_f8)[gq] = f32x4_to_f8x4(v.x, v.y, v.z, v.w);
        __half2 n01 = __floats2half2_rn(v.x * rn, v.y * rn);
        __half2 n23 = __floats2half2_rn(v.z * rn, v.w * rn);
        ((uint2*)nout)[gq] = make_uint2(*(uint32_t*)&n01, *(uint32_t*)&n23);
    }
}

// ---------------- scoring: warp per sample ----------------
__global__ void k_score(const int* __restrict__ user, const int* __restrict__ pos,
                        const int* __restrict__ neg, const float* __restrict__ ue,
                        const float* __restrict__ ie, int U, int B, int L, float* out) {
    int wg = (blockIdx.x * blockDim.x + threadIdx.x) >> 5;
    int lane = threadIdx.x & 31;
    if (wg >= B) return;
    int u = user[wg], p = pos[wg], nn = neg[wg];
    float dp = 0.f, dn = 0.f, sq = 0.f;
    {
        float4 uv = ((const float4*)(ue + (size_t)u * D))[lane];
        float4 pv = ((const float4*)(ie + (size_t)p * D))[lane];
        float4 nv = ((const float4*)(ie + (size_t)nn * D))[lane];
        dp += uv.x * pv.x + uv.y * pv.y + uv.z * pv.z + uv.w * pv.w;
        dn += uv.x * nv.x + uv.y * nv.y + uv.z * nv.z + uv.w * nv.w;
        sq += pv.x * pv.x + pv.y * pv.y + pv.z * pv.z + pv.w * pv.w;
        sq += nv.x * nv.x + nv.y * nv.y + nv.z * nv.z + nv.w * nv.w;
    }
    for (int l = 0; l < L; l++) {
        const uint2* base = (const uint2*)(g_norm_h + (size_t)l * NMAX * D);
        uint2 uh = __ldg(&base[(size_t)u * 32 + lane]);
        uint2 ph = __ldg(&base[(size_t)(U + p) * 32 + lane]);
        uint2 nh = __ldg(&base[(size_t)(U + nn) * 32 + lane]);
        float2 u0 = __half22float2(*(__half2*)&uh.x), u1 = __half22float2(*(__half2*)&uh.y);
        float2 p0 = __half22float2(*(__half2*)&ph.x), p1 = __half22float2(*(__half2*)&ph.y);
        float2 n0 = __half22float2(*(__half2*)&nh.x), n1 = __half22float2(*(__half2*)&nh.y);
        dp += u0.x * p0.x + u0.y * p0.y + u1.x * p1.x + u1.y * p1.y;
        dn += u0.x * n0.x + u0.y * n0.y + u1.x * n1.x + u1.y * n1.y;
    }
    float d = dn - dp;
#pragma unroll
    for (int o = 16; o > 0; o >>= 1) {
        d += __shfl_xor_sync(0xffffffffu, d, o);
        sq += __shfl_xor_sync(0xffffffffu, sq, o);
    }
    if (lane == 0) {
        float sp = fmaxf(d, 0.f) + log1pf(expf(-fabsf(d)));
        atomicAdd(&out[0], sp / (float)B);
        atomicAdd(&out[1], REG_LAMBDA * 0.5f * sq / (float)B);
    }
}

// ---------------- launch ----------------
extern "C" void kernel_launch(void* const* d_in, const int* in_sizes, int n_in,
                              void* d_out, int out_size) {
    const int*   user     = (const int*)d_in[0];
    const int*   positive = (const int*)d_in[1];
    const int*   negative = (const int*)d_in[2];
    const int*   edge_row = (const int*)d_in[3];
    const int*   edge_col = (const int*)d_in[4];
    const float* edge_val = (const float*)d_in[5];
    const float* user_emb = (const float*)d_in[6];
    const float* item_emb = (const float*)d_in[7];
    const float* W_gcn    = (const float*)d_in[8];
    const float* b_gcn    = (const float*)d_in[9];
    const float* W_bi     = (const float*)d_in[10];
    const float* b_bi     = (const float*)d_in[11];
    float* out = (float*)d_out;

    int B   = in_sizes[0];
    int nnz = in_sizes[3];
    int U   = in_sizes[6] / D;
    int I   = in_sizes[7] / D;
    int N   = U + I;
    int L   = in_sizes[9] / D;
    if (L > LBUF) L = LBUF;

    static int attr_done = 0;
    if (!attr_done) {
        cudaFuncSetAttribute(k_layer, cudaFuncAttributeMaxDynamicSharedMemorySize, SM_TOTAL);
        attr_done = 1;
    }

    k_init<<<1024, 256>>>(user_emb, item_emb, edge_row, nnz, U, I, out);
    int nb = (N + 1023) / 1024;
    k_scan_blocks<<<nb, 1024>>>(N);
    k_scan_sums<<<1, 256>>>(nb);
    k_finalize<<<(N + 255) / 256, 256>>>(N, nnz);
    k_fill<<<2048, 256>>>(edge_row, edge_col, edge_val, nnz);
    k_prep<<<(L * 32768 + 255) / 256, 256>>>(W_gcn, W_bi, L);

    int tiles = (N + 127) / 128;
    for (int l = 0; l < L; l++) {
        k_spmm<<<(N * 32 + 255) / 256, 256>>>(N);
        k_layer<<<tiles, 256, SM_TOTAL>>>(b_gcn + (size_t)l * D, b_bi + (size_t)l * D, l, N);
    }
    k_score<<<(B * 32 + 255) / 256, 256>>>(user, positive, negative, user_emb, item_emb,
                                           U, B, L, out);
}

// round 13
// speedup vs baseline: 1.1441x; 1.1441x over previous
#include <cuda_runtime.h>
#include <cuda_fp16.h>
#include <math.h>
#include <cstdint>

#define D 128
#define NMAX 150000
#define NNZMAX 4800000
#define LBUF 4
#define NEG_SLOPE 0.2f
#define REG_LAMBDA 1e-4f
#define PADK 136   // smem row stride (fp16 elems) for conflict-free ldmatrix
#define PADS 132   // stage row stride (fp32 elems)

// ---------------- static device scratch ----------------
__device__ uint8_t g_ego_f8[(size_t)NMAX * D];          // working embeddings (e4m3)
__device__ __half  g_side_h[(size_t)NMAX * D];          // A @ ego (fp16)
__device__ __half  g_norm_h[(size_t)LBUF * NMAX * D];   // normalized per-layer outputs (fp16)
__device__ int     g_rowptr[NMAX + 1];
__device__ int     g_counts[NMAX];                      // zero at module load; re-zeroed by k_finalize
__device__ int     g_cursor[NMAX];
__device__ int2    g_cv[NNZMAX];
__device__ int     g_scanex[NMAX + 1024];
__device__ int     g_blocksums[1024];
__device__ int     g_blockoff[1024];
// weights fp16, n-major: [layer][chunk(Wg/Wb)][n][k]
__device__ __half  g_Bw[(size_t)LBUF * 2 * 16384];

// ---------------- helpers ----------------
__device__ __forceinline__ uint32_t smem_u32(const void* p) {
    uint32_t a;
    asm("{ .reg .u64 t; cvta.to.shared.u64 t, %1; cvt.u32.u64 %0, t; }" : "=r"(a) : "l"(p));
    return a;
}
__device__ __forceinline__ void ldmx4(uint32_t& r0, uint32_t& r1, uint32_t& r2, uint32_t& r3,
                                      uint32_t addr) {
    asm volatile("ldmatrix.sync.aligned.m8n8.x4.shared.b16 {%0,%1,%2,%3}, [%4];"
                 : "=r"(r0), "=r"(r1), "=r"(r2), "=r"(r3) : "r"(addr));
}
__device__ __forceinline__ void mma_f16(float* c, const uint32_t* a, const uint32_t* b) {
    asm volatile(
        "mma.sync.aligned.m16n8k16.row.col.f32.f16.f16.f32 "
        "{%0,%1,%2,%3}, {%4,%5,%6,%7}, {%8,%9}, {%0,%1,%2,%3};"
        : "+f"(c[0]), "+f"(c[1]), "+f"(c[2]), "+f"(c[3])
        : "r"(a[0]), "r"(a[1]), "r"(a[2]), "r"(a[3]), "r"(b[0]), "r"(b[1]));
}
// expand 4 packed e4m3 (u32) -> two f16x2 (column order preserved)
__device__ __forceinline__ void f8x4_to_h2x2(uint32_t in, uint32_t& f0, uint32_t& f1) {
    asm("{ .reg .b16 lo, hi;\n\t"
        "mov.b32 {lo, hi}, %2;\n\t"
        "cvt.rn.f16x2.e4m3x2 %0, lo;\n\t"
        "cvt.rn.f16x2.e4m3x2 %1, hi; }"
        : "=r"(f0), "=r"(f1) : "r"(in));
}
// pack 4 floats -> 4 e4m3 bytes (v0 lowest byte)
__device__ __forceinline__ uint32_t f32x4_to_f8x4(float v0, float v1, float v2, float v3) {
    uint16_t lo, hi;
    asm("cvt.rn.satfinite.e4m3x2.f32 %0, %1, %2;" : "=h"(lo) : "f"(v1), "f"(v0));
    asm("cvt.rn.satfinite.e4m3x2.f32 %0, %1, %2;" : "=h"(hi) : "f"(v3), "f"(v2));
    return (uint32_t)lo | ((uint32_t)hi << 16);
}

// ---------------- init: e4m3 ego, edge count (counts pre-zeroed), zero out ----------------
__global__ void k_init(const float* __restrict__ ue, const float* __restrict__ ie,
                       const int* __restrict__ er, int nnz, int U, int I, float* out) {
    size_t uN = (size_t)U * D;
    size_t n  = (size_t)(U + I) * D;
    for (size_t i4 = (size_t)blockIdx.x * blockDim.x + threadIdx.x; i4 * 4 < n;
         i4 += (size_t)gridDim.x * blockDim.x) {
        size_t i = i4 * 4;  // uN is a multiple of 128, chunks never straddle
        const float* src = (i < uN) ? (ue + i) : (ie + (i - uN));
        float4 v = *(const float4*)src;
        ((uint32_t*)g_ego_f8)[i4] = f32x4_to_f8x4(v.x, v.y, v.z, v.w);
    }
    for (int e = blockIdx.x * blockDim.x + threadIdx.x; e < nnz; e += gridDim.x * blockDim.x)
        atomicAdd(&g_counts[er[e]], 1);
    if (blockIdx.x == 0 && threadIdx.x < 2) out[threadIdx.x] = 0.f;
}

// ---------------- CSR build ----------------
__global__ void k_scan_blocks(int N) {
    int i = blockIdx.x * 1024 + threadIdx.x;
    int c = (i < N) ? g_counts[i] : 0;
    int lane = threadIdx.x & 31, warp = threadIdx.x >> 5;
    int v = c;
#pragma unroll
    for (int o = 1; o < 32; o <<= 1) {
        int t = __shfl_up_sync(0xffffffffu, v, o);
        if (lane >= o) v += t;
    }
    __shared__ int wsum[32];
    if (lane == 31) wsum[warp] = v;
    __syncthreads();
    if (warp == 0) {
        int w = wsum[lane];
#pragma unroll
        for (int o = 1; o < 32; o <<= 1) {
            int t = __shfl_up_sync(0xffffffffu, w, o);
            if (lane >= o) w += t;
        }
        wsum[lane] = w;
    }
    __syncthreads();
    int woff = (warp > 0) ? wsum[warp - 1] : 0;
    g_scanex[i] = v + woff - c;
    if (threadIdx.x == 0) g_blocksums[blockIdx.x] = wsum[31];
}
__global__ void k_scan_sums(int nb) {
    int t = threadIdx.x;
    int v = (t < nb) ? g_blocksums[t] : 0;
    int lane = t & 31, warp = t >> 5;
    int x = v;
#pragma unroll
    for (int o = 1; o < 32; o <<= 1) {
        int s = __shfl_up_sync(0xffffffffu, x, o);
        if (lane >= o) x += s;
    }
    __shared__ int wsum[8];
    if (lane == 31) wsum[warp] = x;
    __syncthreads();
    if (warp == 0 && lane < 8) {
        int w = wsum[lane];
#pragma unroll
        for (int o = 1; o < 8; o <<= 1) {
            int s = __shfl_up_sync(0xffu, w, o);
            if (lane >= o) w += s;
        }
        wsum[lane] = w;
    }
    __syncthreads();
    int woff = (warp > 0) ? wsum[warp - 1] : 0;
    if (t < nb) g_blockoff[t] = (x + woff) - v;
}
__global__ void k_finalize(int N, int nnz) {
    int gid = blockIdx.x * blockDim.x + threadIdx.x;
    for (int i = gid; i < N; i += gridDim.x * blockDim.x) {
        int r = g_scanex[i] + g_blockoff[i >> 10];
        g_rowptr[i] = r;
        g_cursor[i] = r;
        g_counts[i] = 0;  // re-zero for next replay (k_init counts into these)
    }
    if (gid == 0) g_rowptr[N] = nnz;
}
__global__ void k_fill(const int* __restrict__ er, const int* __restrict__ ec,
                       const float* __restrict__ ev, int nnz) {
    for (int e = blockIdx.x * blockDim.x + threadIdx.x; e < nnz; e += gridDim.x * blockDim.x) {
        int r = er[e];
        int pos = atomicAdd(&g_cursor[r], 1);
        g_cv[pos] = make_int2(ec[e], __float_as_int(ev[e]));
    }
}

// ---------------- weight prep: fp16 n-major B images ----------------
__global__ void k_prep(const float* __restrict__ Wg, const float* __restrict__ Wb, int L) {
    int idx = blockIdx.x * blockDim.x + threadIdx.x;
    int tot = L * 2 * 16384;
    if (idx >= tot) return;
    int l = idx / 32768;
    int rem = idx - l * 32768;
    int c = rem >> 14;
    int e = rem & 16383;
    int k = e >> 7, n = e & 127;
    const float* W = c ? Wb : Wg;
    float w = W[(size_t)l * 16384 + k * 128 + n];
    g_Bw[(size_t)(l * 2 + c) * 16384 + n * 128 + k] = __float2half(w);
}

// ---------------- SpMM: side = A @ ego (fp8 gather, fp16 hfma2 acc), half-warp per edge ----------------
__global__ void k_spmm(int N) {
    int gw = (blockIdx.x * blockDim.x + threadIdx.x) >> 5;
    if (gw >= N) return;
    int lane = threadIdx.x & 31;
    int hw = lane >> 4, hl = lane & 15;
    int s = g_rowptr[gw], e = g_rowptr[gw + 1];
    const uint2* ego8 = (const uint2*)g_ego_f8;  // 8 e4m3 per uint2; row = 16 uint2 (128B)
    __half2 acc[4];
#pragma unroll
    for (int q = 0; q < 4; q++) acc[q] = __half2half2(__ushort_as_half(0));
#pragma unroll 4
    for (int j = s + hw; j < e; j += 2) {
        int2 cv = __ldg(&g_cv[j]);
        __half2 vh = __float2half2_rn(__int_as_float(cv.y));
        uint2 h = __ldg(&ego8[(size_t)cv.x * 16 + hl]);
        uint32_t f0, f1, f2, f3;
        f8x4_to_h2x2(h.x, f0, f1);
        f8x4_to_h2x2(h.y, f2, f3);
        acc[0] = __hfma2(vh, *(__half2*)&f0, acc[0]);
        acc[1] = __hfma2(vh, *(__half2*)&f1, acc[1]);
        acc[2] = __hfma2(vh, *(__half2*)&f2, acc[2]);
        acc[3] = __hfma2(vh, *(__half2*)&f3, acc[3]);
    }
    // combine the two halves
#pragma unroll
    for (int q = 0; q < 4; q++) {
        uint32_t u = *(uint32_t*)&acc[q];
        uint32_t o = __shfl_xor_sync(0xffffffffu, u, 16);
        acc[q] = __hadd2(acc[q], *(__half2*)&o);
    }
    if (hw == 0) {
        ((uint4*)g_side_h)[(size_t)gw * 16 + hl] =
            make_uint4(*(uint32_t*)&acc[0], *(uint32_t*)&acc[1],
                       *(uint32_t*)&acc[2], *(uint32_t*)&acc[3]);
    }
}

// ---------------- fused dense layer via mma.sync fp16 ----------------
// smem: [0,512) bias | [512,1024) srn | A(34816) | B(34816)  => 70656 B, 2 CTAs/SM
#define SM_HDR   1024
#define SM_A     SM_HDR
#define SM_B     (SM_HDR + 34816)
#define SM_TOTAL (SM_HDR + 69632)
// stage (fp32, stride PADS): 128*132*4 = 67584 <= 69632, overlaps A+B post-MMA

__global__ void __launch_bounds__(256, 2) k_layer(const float* __restrict__ bg,
                                                  const float* __restrict__ bb,
                                                  int layer, int N) {
    extern __shared__ char sm[];
    uint32_t smb = smem_u32(sm);
    int tid = threadIdx.x;
    int warp = tid >> 5, lane = tid & 31;
    int row0 = blockIdx.x * 128;

    if (tid < 128) ((float*)sm)[tid] = bg[tid] + bb[tid];

    int rw0 = (warp >> 1) * 32;
    int cw0 = (warp & 1) * 64;

    float cacc[2][8][4];
#pragma unroll
    for (int mt = 0; mt < 2; mt++)
#pragma unroll
        for (int nt = 0; nt < 8; nt++)
#pragma unroll
            for (int q = 0; q < 4; q++) cacc[mt][nt][q] = 0.f;

    for (int chunk = 0; chunk < 2; chunk++) {
        if (chunk) __syncthreads();
        // weights (fp16), pad rows to PADK
        {
            const __half* src = g_Bw + (size_t)(layer * 2 + chunk) * 16384;
            for (int i = tid; i < 2048; i += 256) {
                int n = i >> 4, k8 = (i & 15) * 8;
                *(uint4*)(sm + SM_B + (n * PADK + k8) * 2) = *(const uint4*)(src + n * 128 + k8);
            }
        }
        // A tile: chunk0 = side (fp16 copy), chunk1 = ego(fp8->fp16) * side
        if (chunk == 0) {
            const uint4* s16 = (const uint4*)g_side_h;
            for (int i = tid; i < 2048; i += 256) {
                int r = i >> 4, c = i & 15;
                int gr = row0 + r;
                uint4 v = make_uint4(0u, 0u, 0u, 0u);
                if (gr < N) v = __ldg(&s16[(size_t)gr * 16 + c]);
                *(uint4*)(sm + SM_A + (r * PADK + c * 8) * 2) = v;
            }
        } else {
            const uint4* s16 = (const uint4*)g_side_h;
            const uint2* e8  = (const uint2*)g_ego_f8;
            for (int i = tid; i < 2048; i += 256) {
                int r = i >> 4, c = i & 15;
                int gr = row0 + r;
                uint4 v = make_uint4(0u, 0u, 0u, 0u);
                if (gr < N) {
                    uint4 sv = __ldg(&s16[(size_t)gr * 16 + c]);
                    uint2 ev = __ldg(&e8[(size_t)gr * 16 + c]);
                    uint32_t e0, e1, e2, e3;
                    f8x4_to_h2x2(ev.x, e0, e1);
                    f8x4_to_h2x2(ev.y, e2, e3);
                    __half2* sp = (__half2*)&sv;
                    sp[0] = __hmul2(sp[0], *(__half2*)&e0);
                    sp[1] = __hmul2(sp[1], *(__half2*)&e1);
                    sp[2] = __hmul2(sp[2], *(__half2*)&e2);
                    sp[3] = __hmul2(sp[3], *(__half2*)&e3);
                    v = sv;
                }
                *(uint4*)(sm + SM_A + (r * PADK + c * 8) * 2) = v;
            }
        }
        __syncthreads();

        int t = lane >> 3, rr = lane & 7;
        int roff = (t & 1) * 8 + rr;
        int koff = (t >> 1) * 8;
#pragma unroll
        for (int kk = 0; kk < 8; kk++) {
            int k0 = kk * 16 + koff;
            uint32_t ah[2][4];
#pragma unroll
            for (int mt = 0; mt < 2; mt++) {
                uint32_t a = smb + SM_A + ((rw0 + mt * 16 + roff) * PADK + k0) * 2;
                ldmx4(ah[mt][0], ah[mt][1], ah[mt][2], ah[mt][3], a);
            }
            uint32_t bh[8][2];
#pragma unroll
            for (int np = 0; np < 4; np++) {
                uint32_t a = smb + SM_B + ((cw0 + np * 16 + roff) * PADK + k0) * 2;
                uint32_t r0, r1, r2, r3;
                ldmx4(r0, r1, r2, r3, a);
                bh[np * 2][0] = r0; bh[np * 2][1] = r2;
                bh[np * 2 + 1][0] = r1; bh[np * 2 + 1][1] = r3;
            }
#pragma unroll
            for (int mt = 0; mt < 2; mt++)
#pragma unroll
                for (int nt = 0; nt < 8; nt++) mma_f16(cacc[mt][nt], ah[mt], bh[nt]);
        }
    }
    __syncthreads();

    // epilogue: bias + leaky-relu -> stage
    float* stage = (float*)(sm + SM_HDR);
    const float* sbias = (const float*)sm;
    float* srn = (float*)(sm + 512);
    int g = lane >> 2, tig = lane & 3;
#pragma unroll
    for (int mt = 0; mt < 2; mt++)
#pragma unroll
        for (int nt = 0; nt < 8; nt++) {
            int col = cw0 + nt * 8 + tig * 2;
            int r0 = rw0 + mt * 16 + g;
            float b0 = sbias[col], b1 = sbias[col + 1];
            float v0 = cacc[mt][nt][0] + b0;
            float v1 = cacc[mt][nt][1] + b1;
            float v2 = cacc[mt][nt][2] + b0;
            float v3 = cacc[mt][nt][3] + b1;
            v0 = (v0 > 0.f) ? v0 : NEG_SLOPE * v0;
            v1 = (v1 > 0.f) ? v1 : NEG_SLOPE * v1;
            v2 = (v2 > 0.f) ? v2 : NEG_SLOPE * v2;
            v3 = (v3 > 0.f) ? v3 : NEG_SLOPE * v3;
            stage[r0 * PADS + col] = v0;
            stage[r0 * PADS + col + 1] = v1;
            stage[(r0 + 8) * PADS + col] = v2;
            stage[(r0 + 8) * PADS + col + 1] = v3;
        }
    __syncthreads();

    // row norms: warp w -> rows [w*16, w*16+16)
    for (int rr = 0; rr < 16; rr++) {
        int r = warp * 16 + rr;
        float4 x = *(float4*)&stage[r * PADS + lane * 4];
        float ss = x.x * x.x + x.y * x.y + x.z * x.z + x.w * x.w;
#pragma unroll
        for (int o = 16; o > 0; o >>= 1) ss += __shfl_xor_sync(0xffffffffu, ss, o);
        if (lane == 0) srn[r] = 1.f / fmaxf(sqrtf(ss), 1e-12f);
    }
    __syncthreads();

    // writeout: ego (e4m3) + norm (fp16)
    int rows = N - row0;
    if (rows > 128) rows = 128;
    __half* nout = g_norm_h + (size_t)layer * NMAX * D;
    for (int idx = tid; idx < rows * 32; idx += 256) {
        int r = idx >> 5, q = idx & 31;
        float4 v = *(float4*)&stage[r * PADS + q * 4];
        float rn = srn[r];
        size_t gq = (size_t)(row0 + r) * 32 + q;
        ((uint32_t*)g_ego_f8)[gq] = f32x4_to_f8x4(v.x, v.y, v.z, v.w);
        __half2 n01 = __floats2half2_rn(v.x * rn, v.y * rn);
        __half2 n23 = __floats2half2_rn(v.z * rn, v.w * rn);
        ((uint2*)nout)[gq] = make_uint2(*(uint32_t*)&n01, *(uint32_t*)&n23);
    }
}

// ---------------- scoring: warp per sample ----------------
__global__ void k_score(const int* __restrict__ user, const int* __restrict__ pos,
                        const int* __restrict__ neg, const float* __restrict__ ue,
                        const float* __restrict__ ie, int U, int B, int L, float* out) {
    int wg = (blockIdx.x * blockDim.x + threadIdx.x) >> 5;
    int lane = threadIdx.x & 31;
    if (wg >= B) return;
    int u = user[wg], p = pos[wg], nn = neg[wg];
    float dp = 0.f, dn = 0.f, sq = 0.f;
    {
        float4 uv = ((const float4*)(ue + (size_t)u * D))[lane];
        float4 pv = ((const float4*)(ie + (size_t)p * D))[lane];
        float4 nv = ((const float4*)(ie + (size_t)nn * D))[lane];
        dp += uv.x * pv.x + uv.y * pv.y + uv.z * pv.z + uv.w * pv.w;
        dn += uv.x * nv.x + uv.y * nv.y + uv.z * nv.z + uv.w * nv.w;
        sq += pv.x * pv.x + pv.y * pv.y + pv.z * pv.z + pv.w * pv.w;
        sq += nv.x * nv.x + nv.y * nv.y + nv.z * nv.z + nv.w * nv.w;
    }
    for (int l = 0; l < L; l++) {
        const uint2* base = (const uint2*)(g_norm_h + (size_t)l * NMAX * D);
        uint2 uh = __ldg(&base[(size_t)u * 32 + lane]);
        uint2 ph = __ldg(&base[(size_t)(U + p) * 32 + lane]);
        uint2 nh = __ldg(&base[(size_t)(U + nn) * 32 + lane]);
        float2 u0 = __half22float2(*(__half2*)&uh.x), u1 = __half22float2(*(__half2*)&uh.y);
        float2 p0 = __half22float2(*(__half2*)&ph.x), p1 = __half22float2(*(__half2*)&ph.y);
        float2 n0 = __half22float2(*(__half2*)&nh.x), n1 = __half22float2(*(__half2*)&nh.y);
        dp += u0.x * p0.x + u0.y * p0.y + u1.x * p1.x + u1.y * p1.y;
        dn += u0.x * n0.x + u0.y * n0.y + u1.x * n1.x + u1.y * n1.y;
    }
    float d = dn - dp;
#pragma unroll
    for (int o = 16; o > 0; o >>= 1) {
        d += __shfl_xor_sync(0xffffffffu, d, o);
        sq += __shfl_xor_sync(0xffffffffu, sq, o);
    }
    if (lane == 0) {
        float sp = fmaxf(d, 0.f) + log1pf(expf(-fabsf(d)));
        atomicAdd(&out[0], sp / (float)B);
        atomicAdd(&out[1], REG_LAMBDA * 0.5f * sq / (float)B);
    }
}

// ---------------- launch ----------------
extern "C" void kernel_launch(void* const* d_in, const int* in_sizes, int n_in,
                              void* d_out, int out_size) {
    const int*   user     = (const int*)d_in[0];
    const int*   positive = (const int*)d_in[1];
    const int*   negative = (const int*)d_in[2];
    const int*   edge_row = (const int*)d_in[3];
    const int*   edge_col = (const int*)d_in[4];
    const float* edge_val = (const float*)d_in[5];
    const float* user_emb = (const float*)d_in[6];
    const float* item_emb = (const float*)d_in[7];
    const float* W_gcn    = (const float*)d_in[8];
    const float* b_gcn    = (const float*)d_in[9];
    const float* W_bi     = (const float*)d_in[10];
    const float* b_bi     = (const float*)d_in[11];
    float* out = (float*)d_out;

    int B   = in_sizes[0];
    int nnz = in_sizes[3];
    int U   = in_sizes[6] / D;
    int I   = in_sizes[7] / D;
    int N   = U + I;
    int L   = in_sizes[9] / D;
    if (L > LBUF) L = LBUF;

    static int attr_done = 0;
    if (!attr_done) {
        cudaFuncSetAttribute(k_layer, cudaFuncAttributeMaxDynamicSharedMemorySize, SM_TOTAL);
        attr_done = 1;
    }

    k_init<<<1024, 256>>>(user_emb, item_emb, edge_row, nnz, U, I, out);
    int nb = (N + 1023) / 1024;
    k_scan_blocks<<<nb, 1024>>>(N);
    k_scan_sums<<<1, 256>>>(nb);
    k_finalize<<<(N + 255) / 256, 256>>>(N, nnz);
    k_fill<<<2048, 256>>>(edge_row, edge_col, edge_val, nnz);
    k_prep<<<(L * 32768 + 255) / 256, 256>>>(W_gcn, W_bi, L);

    int tiles = (N + 127) / 128;
    for (int l = 0; l < L; l++) {
        k_spmm<<<(N * 32 + 255) / 256, 256>>>(N);
        k_layer<<<tiles, 256, SM_TOTAL>>>(b_gcn + (size_t)l * D, b_bi + (size_t)l * D, l, N);
    }
    k_score<<<(B * 32 + 255) / 256, 256>>>(user, positive, negative, user_emb, item_emb,
                                           U, B, L, out);
}